// round 12
// baseline (speedup 1.0000x reference)
#include <cuda_runtime.h>
#include <cuda_bf16.h>
#include <math.h>

#define BATCH 2048
#define NSITE 100
#define DIM   128
#define NORB  400
#define NOCC  50
#define KDET  4

#define TAB_OUT   ((4 + NSITE) * NORB)
#define TAB_BLK   ((TAB_OUT + 255) / 256)     // 163
#define IDX_BLK   ((BATCH + 255) / 256)       // 8

// ---- scratch (static device globals) ----
__device__ float g_TW[4 * NORB];
__device__ float g_PW[NSITE * NORB];
__device__ short g_site[2][BATCH][NOCC];
__device__ unsigned char g_tok[2][BATCH][NOCC];
__device__ float  g_logdet[2][BATCH][KDET];   // log2 |det|
__device__ float  g_sgndet[2][BATCH][KDET];   // -1/0/+1

__device__ const void*  g_cfgp;
__device__ const void*  g_tokp;
__device__ const void*  g_posp;
__device__ const void*  g_Wp;
__device__ const void*  g_biasp;
__device__ int g_is64;
__device__ int g_isbf16;

struct InArgs { const void* p[8]; long long sz[8]; int n; };

__device__ __forceinline__ float ld_f(const void* p, int i, int bf16) {
    if (bf16) return __bfloat162float(((const __nv_bfloat16*)p)[i]);
    return ((const float*)p)[i];
}

// ---------------------------------------------------------------------------
// Warp-parallel content classification of inputs (was single-thread serial).
__global__ void k_resolve(InArgs a) {
    const unsigned FULL = 0xffffffffu;
    int lane = threadIdx.x;

    bool p64f[8], p32f[8], allzf[8], smallf[8];
    int n = (a.n < 8) ? a.n : 8;

    for (int i = 0; i < n; i++) {
        const unsigned int* w = (const unsigned int*)a.p[i];
        // int64 pattern over first 64 pairs: 2 pairs per lane
        bool p64 = true;
        for (int j = lane; j < 64; j += 32) {
            unsigned lo = w[2 * j], hi = w[2 * j + 1];
            if (lo > 3u || hi != 0u) p64 = false;
        }
        // int32 pattern / all-zero over first 128 words: 4 per lane
        bool p32 = true, allz = true;
        float m = 0.f;
        const float* f = (const float*)a.p[i];
        for (int j = lane; j < 128; j += 32) {
            unsigned v = w[j];
            if (v > 3u) p32 = false;
            if (v != 0u) allz = false;
            m += fabsf(f[j]);
        }
        p64f[i]  = __all_sync(FULL, p64);
        p32f[i]  = __all_sync(FULL, p32);
        allzf[i] = __all_sync(FULL, allz);
#pragma unroll
        for (int off = 16; off; off >>= 1)
            m += __shfl_xor_sync(FULL, m, off);
        smallf[i] = (m * (1.f / 128.f)) < 0.2f;
    }

    if (lane != 0) return;

    int cfgI = -1, biasI = -1, WI = -1;
    int tabI[8]; int ntab = 0;
    int is64 = 0;
    for (int i = 0; i < n; i++) {
        if (allzf[i])            { if (biasI < 0) biasI = i; continue; }
        if (p64f[i] || p32f[i])  { if (cfgI < 0) { cfgI = i; is64 = p64f[i] ? 1 : 0; } continue; }
        if (smallf[i])           { if (WI < 0) WI = i; continue; }
        if (ntab < 8) tabI[ntab++] = i;
    }

    int tokI = -1, posI = -1;
    if (ntab >= 2) {
        int aI = tabI[0], bI = tabI[1];
        if (a.sz[aI] >= a.sz[bI]) { posI = aI; tokI = bI; }
        else                      { posI = bI; tokI = aI; }
    } else if (ntab == 1) { tokI = posI = tabI[0]; }

    if (cfgI  < 0) cfgI  = 0;
    if (tokI  < 0) tokI  = (n > 1) ? 1 : 0;
    if (posI  < 0) posI  = (n > 2) ? 2 : 0;
    if (WI    < 0) WI    = (n > 3) ? 3 : 0;
    if (biasI < 0) biasI = (n > 4) ? 4 : 0;

    // f32 vs bf16 plausibility on W (serial but tiny; loads already cached)
    int sane = 0;
    const unsigned short* h = (const unsigned short*)a.p[WI];
    for (int j = 0; j < 128; j++) {
        __nv_bfloat16 bl = *(const __nv_bfloat16*)&h[2 * j];
        float v = fabsf(__bfloat162float(bl));
        if (v >= 1e-6f && v <= 1e3f) sane++;
    }
    g_isbf16 = (sane > 64) ? 1 : 0;

    g_cfgp  = a.p[cfgI];
    g_tokp  = a.p[tokI];
    g_posp  = a.p[posI];
    g_Wp    = a.p[WI];
    g_biasp = a.p[biasI];
    g_is64  = is64;
}

// ---------------------------------------------------------------------------
__global__ void k_prep() {
    int bf = g_isbf16;
    if (blockIdx.x < TAB_BLK) {
        int t = blockIdx.x * 256 + threadIdx.x;
        if (t >= TAB_OUT) return;
        int r = t / NORB;
        int o = t - r * NORB;
        int sbase = (r < 4) ? r * DIM : (r - 4) * DIM;
        const void* src = (r < 4) ? g_tokp : g_posp;
        float acc = 0.f;
#pragma unroll 8
        for (int d = 0; d < DIM; d++)
            acc = fmaf(ld_f(src, sbase + d, bf), ld_f(g_Wp, o * DIM + d, bf), acc);
        if (r < 4) g_TW[r * NORB + o] = acc;
        else       g_PW[(r - 4) * NORB + o] = acc + ld_f(g_biasp, o, bf);
        return;
    }

    int b = (blockIdx.x - TAB_BLK) * 256 + threadIdx.x;
    if (b >= BATCH) return;

    unsigned char c[NSITE];
    if (g_is64) {
        const long long* p = (const long long*)g_cfgp + (long long)b * NSITE;
        for (int n = 0; n < NSITE; n++) c[n] = (unsigned char)(p[n] & 3);
    } else {
        const int* p = (const int*)g_cfgp + b * NSITE;
        for (int n = 0; n < NSITE; n++) c[n] = (unsigned char)(p[n] & 3);
    }

    for (int spin = 0; spin < 2; spin++) {
        unsigned char bit = spin ? 2 : 1;
        short lst[NOCC];
        int cnt = 0;
        for (int n = 0; n < NSITE && cnt < NOCC; n++)
            if (c[n] & bit) lst[cnt++] = (short)n;
        int c1 = cnt;
        for (int n = 0; n < NSITE && cnt < NOCC; n++)
            if (!(c[n] & bit)) lst[cnt++] = (short)n;
        int p = 0, q = c1;
        for (int o = 0; o < NOCC; o++) {
            short v;
            bool takep = (p < c1) && (q >= NOCC || lst[p] < lst[q]);
            if (takep) v = lst[p++]; else v = lst[q++];
            g_site[spin][b][o] = v;
            g_tok[spin][b][o]  = c[v];
        }
    }
}

// ---------------------------------------------------------------------------
// LU chunk: REDUX.MAX argmax; uniform retired-row masks (no ballots);
// pivot row broadcast via double-buffered smem float4; double pivot product.
template<int NC>
__device__ __forceinline__ void lu_chunk(
    int steps, float (&a)[NOCC], float (&bb)[NOCC],
    unsigned& mask0, unsigned& mask1, bool has1, int lane,
    double& det, int& inv, float4* u4, int& par)
{
    constexpr int NQ = (NC >> 2) + 1;
    const unsigned FULL = 0xffffffffu;

#pragma unroll 1
    for (int s = 0; s < steps; s++) {
        float4* ub = u4 + ((par ^= 1) ? 13 : 0);

        bool alive0 = !((mask0 >> lane) & 1u);
        bool alive1 = has1 && !((mask1 >> lane) & 1u);

        // ---- argmax |col0| over alive rows (key: mag[31:6] | 63-row) ----
        unsigned key = 0u;
        if (alive0)
            key = (__float_as_uint(fabsf(a[0])) & 0xFFFFFFC0u) | (unsigned)(63 - lane);
        if (alive1) {
            unsigned k1 = (__float_as_uint(fabsf(bb[0])) & 0xFFFFFFC0u) | (unsigned)(31 - lane);
            if (k1 > key) key = k1;
        }
        unsigned mx = __reduce_max_sync(FULL, key);
        int p   = 63 - (int)(mx & 63u);        // pivot row, warp-uniform
        int src = p & 31;
        bool top = (p < 32);

        // ---- pivot lane stores its row INCLUDING col0 ----
        if (top) {
            if (lane == src) {
#pragma unroll
                for (int q = 0; q < NQ; q++)
                    ub[q] = make_float4(
                        a[4 * q],
                        (4 * q + 1 <= NC) ? a[4 * q + 1] : 0.f,
                        (4 * q + 2 <= NC) ? a[4 * q + 2] : 0.f,
                        (4 * q + 3 <= NC) ? a[4 * q + 3] : 0.f);
            }
        } else {
            if (lane == src) {
#pragma unroll
                for (int q = 0; q < NQ; q++)
                    ub[q] = make_float4(
                        bb[4 * q],
                        (4 * q + 1 <= NC) ? bb[4 * q + 1] : 0.f,
                        (4 * q + 2 <= NC) ? bb[4 * q + 2] : 0.f,
                        (4 * q + 3 <= NC) ? bb[4 * q + 3] : 0.f);
            }
        }
        __syncwarp();

        // ---- parity from uniform masks (no ballots) ----
        if (top) {
            inv += __popc(mask0 & (0xFFFFFFFEu << p)) + __popc(mask1);
            mask0 |= 1u << p;
        } else {
            inv += __popc(mask1 & (0xFFFFFFFEu << (p - 32)));
            mask1 |= 1u << (p - 32);
        }

        // ---- update ----
        float4 U0 = ub[0];
        float piv = U0.x;
        det *= (double)piv;

        float ninv = -1.0f / piv;
        float ma = a[0]  * ninv;   // pivot row -> -1 (self-zeroes); dead -> 0
        float mb = bb[0] * ninv;

        {
            if (1 <= NC) { a[0] = fmaf(ma, U0.y, a[1]); bb[0] = fmaf(mb, U0.y, bb[1]); }
            if (2 <= NC) { a[1] = fmaf(ma, U0.z, a[2]); bb[1] = fmaf(mb, U0.z, bb[2]); }
            if (3 <= NC) { a[2] = fmaf(ma, U0.w, a[3]); bb[2] = fmaf(mb, U0.w, bb[3]); }
        }
#pragma unroll
        for (int q = 1; q < NQ; q++) {
            float4 U = ub[q];
            {                      a[4 * q - 1] = fmaf(ma, U.x, a[4 * q]);
                                   bb[4 * q - 1]= fmaf(mb, U.x, bb[4 * q]); }
            if (4 * q + 1 <= NC) { a[4 * q]     = fmaf(ma, U.y, a[4 * q + 1]);
                                   bb[4 * q]    = fmaf(mb, U.y, bb[4 * q + 1]); }
            if (4 * q + 2 <= NC) { a[4 * q + 1] = fmaf(ma, U.z, a[4 * q + 2]);
                                   bb[4 * q + 1]= fmaf(mb, U.z, bb[4 * q + 2]); }
            if (4 * q + 3 <= NC) { a[4 * q + 2] = fmaf(ma, U.w, a[4 * q + 3]);
                                   bb[4 * q + 2]= fmaf(mb, U.w, bb[4 * q + 3]); }
        }
        // next step writes the other buffer; its REDUX+syncwarp order reuse
    }
}

// ---------------------------------------------------------------------------
__global__ void __launch_bounds__(32, 12) k_main() {
    __shared__ float4 ubuf[26];

    int idx  = blockIdx.x;
    int b    = idx >> 3;
    int rr   = idx & 7;
    int spin = rr >> 2;
    int kk   = rr & 3;
    int lane = threadIdx.x;

    int r1 = 32 + lane;
    bool has1 = (lane < 18);

    int colbase = spin * 200 + kk * 50;

    int s0 = g_site[spin][b][lane];
    int t0 = g_tok[spin][b][lane];
    int s1 = has1 ? (int)g_site[spin][b][r1] : 0;
    int t1 = has1 ? (int)g_tok[spin][b][r1] : 0;

    const float* TW0 = g_TW + t0 * NORB + colbase;
    const float* PW0 = g_PW + s0 * NORB + colbase;
    const float* TW1 = g_TW + t1 * NORB + colbase;
    const float* PW1 = g_PW + s1 * NORB + colbase;

    float a[NOCC], bb[NOCC];
#pragma unroll
    for (int c = 0; c < NOCC; c++) {
        a[c] = TW0[c] + PW0[c];
        float v1 = TW1[c] + PW1[c];
        bb[c] = has1 ? v1 : 0.f;
    }

    unsigned mask0 = 0u;                       // retired rows 0..31
    unsigned mask1 = 0xFFFFFFFFu << 18;        // rows 50..63 never exist
    double det = 1.0;
    int   inv  = 0;
    int   par  = 0;

    lu_chunk<49>(10, a, bb, mask0, mask1, has1, lane, det, inv, ubuf, par);
    lu_chunk<39>(10, a, bb, mask0, mask1, has1, lane, det, inv, ubuf, par);
    lu_chunk<29>(10, a, bb, mask0, mask1, has1, lane, det, inv, ubuf, par);
    lu_chunk<19>(10, a, bb, mask0, mask1, has1, lane, det, inv, ubuf, par);
    lu_chunk<9> (10, a, bb, mask0, mask1, has1, lane, det, inv, ubuf, par);

    if (lane == 0) {
        float sgn, lmag;
        if (det == 0.0) { sgn = 0.f; lmag = 0.f; }
        else {
            sgn = (det < 0.0) ? -1.f : 1.f;
            if (inv & 1) sgn = -sgn;
            lmag = (float)log2(fabs(det));
        }
        g_logdet[spin][b][kk] = lmag;
        g_sgndet[spin][b][kk] = sgn;
    }
}

// ---------------------------------------------------------------------------
__global__ void k_combine(float* __restrict__ out, int out_elems) {
    int b = blockIdx.x * blockDim.x + threadIdx.x;
    if (b >= BATCH) return;

    float L[KDET], S[KDET];
    float M = -1e30f;
    for (int k = 0; k < KDET; k++) {
        S[k] = g_sgndet[0][b][k] * g_sgndet[1][b][k];
        L[k] = g_logdet[0][b][k] + g_logdet[1][b][k];
        if (S[k] != 0.f && L[k] > M) M = L[k];
    }
    float psis = 0.f;
    for (int k = 0; k < KDET; k++)
        if (S[k] != 0.f) psis += S[k] * exp2f(L[k] - M);

    double apsi = fabs((double)psis) * exp2((double)M);
    float la = (float)log(apsi + 1e-30);
    float ph = (psis >= 0.f) ? 0.f : 3.14159265358979323846f;

    if (out_elems == BATCH) {
        out[b] = la;
    } else {
        out[2 * b]     = la;
        out[2 * b + 1] = ph;
    }
}

// ---------------------------------------------------------------------------
extern "C" void kernel_launch(void* const* d_in, const int* in_sizes, int n_in,
                              void* d_out, int out_size) {
    InArgs a;
    a.n = (n_in < 8) ? n_in : 8;
    for (int i = 0; i < 8; i++) {
        a.p[i]  = (i < n_in) ? d_in[i] : d_in[0];
        a.sz[i] = (i < n_in) ? (long long)in_sizes[i] : 0;
    }

    k_resolve<<<1, 32>>>(a);
    k_prep   <<<TAB_BLK + IDX_BLK, 256>>>();
    k_main   <<<BATCH * 2 * KDET, 32>>>();
    k_combine<<<IDX_BLK, 256>>>((float*)d_out, out_size);
}

// round 13
// speedup vs baseline: 1.0731x; 1.0731x over previous
#include <cuda_runtime.h>
#include <cuda_bf16.h>
#include <math.h>

#define BATCH 2048
#define NSITE 100
#define DIM   128
#define NORB  400
#define NOCC  50
#define KDET  4

#define TAB_OUT   ((4 + NSITE) * NORB)
#define TAB_BLK   ((TAB_OUT + 255) / 256)     // 163
#define IDX_BLK   ((BATCH + 255) / 256)       // 8

// ---- scratch (static device globals) ----
__device__ float g_TW[4 * NORB];
__device__ float g_PW[NSITE * NORB];
__device__ short g_site[2][BATCH][NOCC];
__device__ unsigned char g_tok[2][BATCH][NOCC];
__device__ float  g_logdet[2][BATCH][KDET];   // log2 |det|
__device__ float  g_sgndet[2][BATCH][KDET];   // -1/0/+1

__device__ const void*  g_cfgp;
__device__ const void*  g_tokp;
__device__ const void*  g_posp;
__device__ const void*  g_Wp;
__device__ const void*  g_biasp;
__device__ int g_is64;
__device__ int g_isbf16;

struct InArgs { const void* p[8]; long long sz[8]; int n; };

__device__ __forceinline__ float ld_f(const void* p, int i, int bf16) {
    if (bf16) return __bfloat162float(((const __nv_bfloat16*)p)[i]);
    return ((const float*)p)[i];
}

// ---------------------------------------------------------------------------
// Warp-parallel content classification of inputs.
__global__ void k_resolve(InArgs a) {
    const unsigned FULL = 0xffffffffu;
    int lane = threadIdx.x;

    bool p64f[8], p32f[8], allzf[8], smallf[8];
    int n = (a.n < 8) ? a.n : 8;

    for (int i = 0; i < n; i++) {
        const unsigned int* w = (const unsigned int*)a.p[i];
        bool p64 = true;
        for (int j = lane; j < 64; j += 32) {
            unsigned lo = w[2 * j], hi = w[2 * j + 1];
            if (lo > 3u || hi != 0u) p64 = false;
        }
        bool p32 = true, allz = true;
        float m = 0.f;
        const float* f = (const float*)a.p[i];
        for (int j = lane; j < 128; j += 32) {
            unsigned v = w[j];
            if (v > 3u) p32 = false;
            if (v != 0u) allz = false;
            m += fabsf(f[j]);
        }
        p64f[i]  = __all_sync(FULL, p64);
        p32f[i]  = __all_sync(FULL, p32);
        allzf[i] = __all_sync(FULL, allz);
#pragma unroll
        for (int off = 16; off; off >>= 1)
            m += __shfl_xor_sync(FULL, m, off);
        smallf[i] = (m * (1.f / 128.f)) < 0.2f;
    }

    if (lane != 0) return;

    int cfgI = -1, biasI = -1, WI = -1;
    int tabI[8]; int ntab = 0;
    int is64 = 0;
    for (int i = 0; i < n; i++) {
        if (allzf[i])            { if (biasI < 0) biasI = i; continue; }
        if (p64f[i] || p32f[i])  { if (cfgI < 0) { cfgI = i; is64 = p64f[i] ? 1 : 0; } continue; }
        if (smallf[i])           { if (WI < 0) WI = i; continue; }
        if (ntab < 8) tabI[ntab++] = i;
    }

    int tokI = -1, posI = -1;
    if (ntab >= 2) {
        int aI = tabI[0], bI = tabI[1];
        if (a.sz[aI] >= a.sz[bI]) { posI = aI; tokI = bI; }
        else                      { posI = bI; tokI = aI; }
    } else if (ntab == 1) { tokI = posI = tabI[0]; }

    if (cfgI  < 0) cfgI  = 0;
    if (tokI  < 0) tokI  = (n > 1) ? 1 : 0;
    if (posI  < 0) posI  = (n > 2) ? 2 : 0;
    if (WI    < 0) WI    = (n > 3) ? 3 : 0;
    if (biasI < 0) biasI = (n > 4) ? 4 : 0;

    int sane = 0;
    const unsigned short* h = (const unsigned short*)a.p[WI];
    for (int j = 0; j < 128; j++) {
        __nv_bfloat16 bl = *(const __nv_bfloat16*)&h[2 * j];
        float v = fabsf(__bfloat162float(bl));
        if (v >= 1e-6f && v <= 1e3f) sane++;
    }
    g_isbf16 = (sane > 64) ? 1 : 0;

    g_cfgp  = a.p[cfgI];
    g_tokp  = a.p[tokI];
    g_posp  = a.p[posI];
    g_Wp    = a.p[WI];
    g_biasp = a.p[biasI];
    g_is64  = is64;
}

// ---------------------------------------------------------------------------
__global__ void k_prep() {
    int bf = g_isbf16;
    if (blockIdx.x < TAB_BLK) {
        int t = blockIdx.x * 256 + threadIdx.x;
        if (t >= TAB_OUT) return;
        int r = t / NORB;
        int o = t - r * NORB;
        int sbase = (r < 4) ? r * DIM : (r - 4) * DIM;
        const void* src = (r < 4) ? g_tokp : g_posp;
        float acc = 0.f;
#pragma unroll 8
        for (int d = 0; d < DIM; d++)
            acc = fmaf(ld_f(src, sbase + d, bf), ld_f(g_Wp, o * DIM + d, bf), acc);
        if (r < 4) g_TW[r * NORB + o] = acc;
        else       g_PW[(r - 4) * NORB + o] = acc + ld_f(g_biasp, o, bf);
        return;
    }

    int b = (blockIdx.x - TAB_BLK) * 256 + threadIdx.x;
    if (b >= BATCH) return;

    unsigned char c[NSITE];
    if (g_is64) {
        const long long* p = (const long long*)g_cfgp + (long long)b * NSITE;
        for (int n = 0; n < NSITE; n++) c[n] = (unsigned char)(p[n] & 3);
    } else {
        const int* p = (const int*)g_cfgp + b * NSITE;
        for (int n = 0; n < NSITE; n++) c[n] = (unsigned char)(p[n] & 3);
    }

    for (int spin = 0; spin < 2; spin++) {
        unsigned char bit = spin ? 2 : 1;
        short lst[NOCC];
        int cnt = 0;
        for (int n = 0; n < NSITE && cnt < NOCC; n++)
            if (c[n] & bit) lst[cnt++] = (short)n;
        int c1 = cnt;
        for (int n = 0; n < NSITE && cnt < NOCC; n++)
            if (!(c[n] & bit)) lst[cnt++] = (short)n;
        int p = 0, q = c1;
        for (int o = 0; o < NOCC; o++) {
            short v;
            bool takep = (p < c1) && (q >= NOCC || lst[p] < lst[q]);
            if (takep) v = lst[p++]; else v = lst[q++];
            g_site[spin][b][o] = v;
            g_tok[spin][b][o]  = c[v];
        }
    }
}

// ---------------------------------------------------------------------------
// LU chunk: REDUX.MAX argmax; uniform retired-row masks for parity;
// pivot row broadcast via double-buffered smem float4; FLOAT log2f pivot
// accumulation (NO FP64 in the loop — R12 showed the DMUL chain stalls).
template<int NC>
__device__ __forceinline__ void lu_chunk(
    int steps, float (&a)[NOCC], float (&bb)[NOCC],
    unsigned& mask0, unsigned& mask1, bool has1, int lane,
    float& lmag, int& inv, int& nneg, bool& zerod, float4* u4, int& par)
{
    constexpr int NQ = (NC >> 2) + 1;
    const unsigned FULL = 0xffffffffu;

#pragma unroll 1
    for (int s = 0; s < steps; s++) {
        float4* ub = u4 + ((par ^= 1) ? 13 : 0);

        bool alive0 = !((mask0 >> lane) & 1u);
        bool alive1 = has1 && !((mask1 >> lane) & 1u);

        // ---- argmax |col0| over alive rows (key: mag[31:6] | 63-row) ----
        unsigned key = 0u;
        if (alive0)
            key = (__float_as_uint(fabsf(a[0])) & 0xFFFFFFC0u) | (unsigned)(63 - lane);
        if (alive1) {
            unsigned k1 = (__float_as_uint(fabsf(bb[0])) & 0xFFFFFFC0u) | (unsigned)(31 - lane);
            if (k1 > key) key = k1;
        }
        unsigned mx = __reduce_max_sync(FULL, key);
        int p   = 63 - (int)(mx & 63u);        // pivot row, warp-uniform
        int src = p & 31;
        bool top = (p < 32);

        // ---- pivot lane stores its row INCLUDING col0 ----
        if (top) {
            if (lane == src) {
#pragma unroll
                for (int q = 0; q < NQ; q++)
                    ub[q] = make_float4(
                        a[4 * q],
                        (4 * q + 1 <= NC) ? a[4 * q + 1] : 0.f,
                        (4 * q + 2 <= NC) ? a[4 * q + 2] : 0.f,
                        (4 * q + 3 <= NC) ? a[4 * q + 3] : 0.f);
            }
        } else {
            if (lane == src) {
#pragma unroll
                for (int q = 0; q < NQ; q++)
                    ub[q] = make_float4(
                        bb[4 * q],
                        (4 * q + 1 <= NC) ? bb[4 * q + 1] : 0.f,
                        (4 * q + 2 <= NC) ? bb[4 * q + 2] : 0.f,
                        (4 * q + 3 <= NC) ? bb[4 * q + 3] : 0.f);
            }
        }
        __syncwarp();

        // ---- parity from uniform masks ----
        if (top) {
            inv += __popc(mask0 & (0xFFFFFFFEu << p)) + __popc(mask1);
            mask0 |= 1u << p;
        } else {
            inv += __popc(mask1 & (0xFFFFFFFEu << (p - 32)));
            mask1 |= 1u << (p - 32);
        }

        // ---- update ----
        float4 U0 = ub[0];
        float piv = U0.x;
        if (piv == 0.f) zerod = true;
        lmag += log2f(fabsf(piv));
        nneg += (piv < 0.f) ? 1 : 0;

        float ninv = -1.0f / piv;
        float ma = a[0]  * ninv;   // pivot row -> -1 (self-zeroes); dead -> 0
        float mb = bb[0] * ninv;

        {
            if (1 <= NC) { a[0] = fmaf(ma, U0.y, a[1]); bb[0] = fmaf(mb, U0.y, bb[1]); }
            if (2 <= NC) { a[1] = fmaf(ma, U0.z, a[2]); bb[1] = fmaf(mb, U0.z, bb[2]); }
            if (3 <= NC) { a[2] = fmaf(ma, U0.w, a[3]); bb[2] = fmaf(mb, U0.w, bb[3]); }
        }
#pragma unroll
        for (int q = 1; q < NQ; q++) {
            float4 U = ub[q];
            {                      a[4 * q - 1] = fmaf(ma, U.x, a[4 * q]);
                                   bb[4 * q - 1]= fmaf(mb, U.x, bb[4 * q]); }
            if (4 * q + 1 <= NC) { a[4 * q]     = fmaf(ma, U.y, a[4 * q + 1]);
                                   bb[4 * q]    = fmaf(mb, U.y, bb[4 * q + 1]); }
            if (4 * q + 2 <= NC) { a[4 * q + 1] = fmaf(ma, U.z, a[4 * q + 2]);
                                   bb[4 * q + 1]= fmaf(mb, U.z, bb[4 * q + 2]); }
            if (4 * q + 3 <= NC) { a[4 * q + 2] = fmaf(ma, U.w, a[4 * q + 3]);
                                   bb[4 * q + 2]= fmaf(mb, U.w, bb[4 * q + 3]); }
        }
        // next step writes the other buffer; its REDUX+syncwarp order reuse
    }
}

// ---------------------------------------------------------------------------
__global__ void __launch_bounds__(32, 12) k_main() {
    __shared__ float4 ubuf[26];

    int idx  = blockIdx.x;
    int b    = idx >> 3;
    int rr   = idx & 7;
    int spin = rr >> 2;
    int kk   = rr & 3;
    int lane = threadIdx.x;

    int r1 = 32 + lane;
    bool has1 = (lane < 18);

    int colbase = spin * 200 + kk * 50;

    int s0 = g_site[spin][b][lane];
    int t0 = g_tok[spin][b][lane];
    int s1 = has1 ? (int)g_site[spin][b][r1] : 0;
    int t1 = has1 ? (int)g_tok[spin][b][r1] : 0;

    const float* TW0 = g_TW + t0 * NORB + colbase;
    const float* PW0 = g_PW + s0 * NORB + colbase;
    const float* TW1 = g_TW + t1 * NORB + colbase;
    const float* PW1 = g_PW + s1 * NORB + colbase;

    float a[NOCC], bb[NOCC];
#pragma unroll
    for (int c = 0; c < NOCC; c++) {
        a[c] = TW0[c] + PW0[c];
        float v1 = TW1[c] + PW1[c];
        bb[c] = has1 ? v1 : 0.f;
    }

    unsigned mask0 = 0u;                       // retired rows 0..31
    unsigned mask1 = 0xFFFFFFFFu << 18;        // rows 50..63 never exist
    float lmag = 0.f;
    int   inv  = 0;
    int   nneg = 0;
    bool  zerod = false;
    int   par  = 0;

    lu_chunk<49>(10, a, bb, mask0, mask1, has1, lane, lmag, inv, nneg, zerod, ubuf, par);
    lu_chunk<39>(10, a, bb, mask0, mask1, has1, lane, lmag, inv, nneg, zerod, ubuf, par);
    lu_chunk<29>(10, a, bb, mask0, mask1, has1, lane, lmag, inv, nneg, zerod, ubuf, par);
    lu_chunk<19>(10, a, bb, mask0, mask1, has1, lane, lmag, inv, nneg, zerod, ubuf, par);
    lu_chunk<9> (10, a, bb, mask0, mask1, has1, lane, lmag, inv, nneg, zerod, ubuf, par);

    if (lane == 0) {
        float sgn = zerod ? 0.f : (((inv + nneg) & 1) ? -1.f : 1.f);
        g_logdet[spin][b][kk] = lmag;
        g_sgndet[spin][b][kk] = sgn;
    }
}

// ---------------------------------------------------------------------------
__global__ void k_combine(float* __restrict__ out, int out_elems) {
    int b = blockIdx.x * blockDim.x + threadIdx.x;
    if (b >= BATCH) return;

    float L[KDET], S[KDET];
    float M = -1e30f;
    for (int k = 0; k < KDET; k++) {
        S[k] = g_sgndet[0][b][k] * g_sgndet[1][b][k];
        L[k] = g_logdet[0][b][k] + g_logdet[1][b][k];
        if (S[k] != 0.f && L[k] > M) M = L[k];
    }
    float psis = 0.f;
    for (int k = 0; k < KDET; k++)
        if (S[k] != 0.f) psis += S[k] * exp2f(L[k] - M);

    double apsi = fabs((double)psis) * exp2((double)M);
    float la = (float)log(apsi + 1e-30);
    float ph = (psis >= 0.f) ? 0.f : 3.14159265358979323846f;

    if (out_elems == BATCH) {
        out[b] = la;
    } else {
        out[2 * b]     = la;
        out[2 * b + 1] = ph;
    }
}

// ---------------------------------------------------------------------------
extern "C" void kernel_launch(void* const* d_in, const int* in_sizes, int n_in,
                              void* d_out, int out_size) {
    InArgs a;
    a.n = (n_in < 8) ? n_in : 8;
    for (int i = 0; i < 8; i++) {
        a.p[i]  = (i < n_in) ? d_in[i] : d_in[0];
        a.sz[i] = (i < n_in) ? (long long)in_sizes[i] : 0;
    }

    k_resolve<<<1, 32>>>(a);
    k_prep   <<<TAB_BLK + IDX_BLK, 256>>>();
    k_main   <<<BATCH * 2 * KDET, 32>>>();
    k_combine<<<IDX_BLK, 256>>>((float*)d_out, out_size);
}

// round 14
// speedup vs baseline: 1.1263x; 1.0496x over previous
#include <cuda_runtime.h>
#include <cuda_bf16.h>
#include <math.h>

#define BATCH 2048
#define NSITE 100
#define DIM   128
#define NORB  400
#define NOCC  50
#define KDET  4

#define TAB_OUT   ((4 + NSITE) * NORB)
#define TAB_BLK   ((TAB_OUT + 255) / 256)     // 163
#define IDX_BLK   ((BATCH + 255) / 256)       // 8

// ---- scratch (static device globals) ----
__device__ float g_TW[4 * NORB];
__device__ float g_PW[NSITE * NORB];
__device__ short g_site[2][BATCH][NOCC];
__device__ unsigned char g_tok[2][BATCH][NOCC];
__device__ float  g_logdet[2][BATCH][KDET];   // log2 |det|
__device__ float  g_sgndet[2][BATCH][KDET];   // -1/0/+1

__device__ const void*  g_cfgp;
__device__ const void*  g_tokp;
__device__ const void*  g_posp;
__device__ const void*  g_Wp;
__device__ const void*  g_biasp;
__device__ int g_is64;
__device__ int g_isbf16;

struct InArgs { const void* p[8]; long long sz[8]; int n; };

__device__ __forceinline__ float ld_f(const void* p, int i, int bf16) {
    if (bf16) return __bfloat162float(((const __nv_bfloat16*)p)[i]);
    return ((const float*)p)[i];
}

// ---------------------------------------------------------------------------
// Warp-parallel content classification of inputs.
__global__ void k_resolve(InArgs a) {
    const unsigned FULL = 0xffffffffu;
    int lane = threadIdx.x;

    bool p64f[8], p32f[8], allzf[8], smallf[8];
    int n = (a.n < 8) ? a.n : 8;

    for (int i = 0; i < n; i++) {
        const unsigned int* w = (const unsigned int*)a.p[i];
        bool p64 = true;
        for (int j = lane; j < 64; j += 32) {
            unsigned lo = w[2 * j], hi = w[2 * j + 1];
            if (lo > 3u || hi != 0u) p64 = false;
        }
        bool p32 = true, allz = true;
        float m = 0.f;
        const float* f = (const float*)a.p[i];
        for (int j = lane; j < 128; j += 32) {
            unsigned v = w[j];
            if (v > 3u) p32 = false;
            if (v != 0u) allz = false;
            m += fabsf(f[j]);
        }
        p64f[i]  = __all_sync(FULL, p64);
        p32f[i]  = __all_sync(FULL, p32);
        allzf[i] = __all_sync(FULL, allz);
#pragma unroll
        for (int off = 16; off; off >>= 1)
            m += __shfl_xor_sync(FULL, m, off);
        smallf[i] = (m * (1.f / 128.f)) < 0.2f;
    }

    if (lane != 0) return;

    int cfgI = -1, biasI = -1, WI = -1;
    int tabI[8]; int ntab = 0;
    int is64 = 0;
    for (int i = 0; i < n; i++) {
        if (allzf[i])            { if (biasI < 0) biasI = i; continue; }
        if (p64f[i] || p32f[i])  { if (cfgI < 0) { cfgI = i; is64 = p64f[i] ? 1 : 0; } continue; }
        if (smallf[i])           { if (WI < 0) WI = i; continue; }
        if (ntab < 8) tabI[ntab++] = i;
    }

    int tokI = -1, posI = -1;
    if (ntab >= 2) {
        int aI = tabI[0], bI = tabI[1];
        if (a.sz[aI] >= a.sz[bI]) { posI = aI; tokI = bI; }
        else                      { posI = bI; tokI = aI; }
    } else if (ntab == 1) { tokI = posI = tabI[0]; }

    if (cfgI  < 0) cfgI  = 0;
    if (tokI  < 0) tokI  = (n > 1) ? 1 : 0;
    if (posI  < 0) posI  = (n > 2) ? 2 : 0;
    if (WI    < 0) WI    = (n > 3) ? 3 : 0;
    if (biasI < 0) biasI = (n > 4) ? 4 : 0;

    int sane = 0;
    const unsigned short* h = (const unsigned short*)a.p[WI];
    for (int j = 0; j < 128; j++) {
        __nv_bfloat16 bl = *(const __nv_bfloat16*)&h[2 * j];
        float v = fabsf(__bfloat162float(bl));
        if (v >= 1e-6f && v <= 1e3f) sane++;
    }
    g_isbf16 = (sane > 64) ? 1 : 0;

    g_cfgp  = a.p[cfgI];
    g_tokp  = a.p[tokI];
    g_posp  = a.p[posI];
    g_Wp    = a.p[WI];
    g_biasp = a.p[biasI];
    g_is64  = is64;
}

// ---------------------------------------------------------------------------
__global__ void k_prep() {
    int bf = g_isbf16;
    if (blockIdx.x < TAB_BLK) {
        int t = blockIdx.x * 256 + threadIdx.x;
        if (t >= TAB_OUT) return;
        int r = t / NORB;
        int o = t - r * NORB;
        int sbase = (r < 4) ? r * DIM : (r - 4) * DIM;
        const void* src = (r < 4) ? g_tokp : g_posp;
        float acc = 0.f;
#pragma unroll 8
        for (int d = 0; d < DIM; d++)
            acc = fmaf(ld_f(src, sbase + d, bf), ld_f(g_Wp, o * DIM + d, bf), acc);
        if (r < 4) g_TW[r * NORB + o] = acc;
        else       g_PW[(r - 4) * NORB + o] = acc + ld_f(g_biasp, o, bf);
        return;
    }

    int b = (blockIdx.x - TAB_BLK) * 256 + threadIdx.x;
    if (b >= BATCH) return;

    unsigned char c[NSITE];
    if (g_is64) {
        const long long* p = (const long long*)g_cfgp + (long long)b * NSITE;
        for (int n = 0; n < NSITE; n++) c[n] = (unsigned char)(p[n] & 3);
    } else {
        const int* p = (const int*)g_cfgp + b * NSITE;
        for (int n = 0; n < NSITE; n++) c[n] = (unsigned char)(p[n] & 3);
    }

    for (int spin = 0; spin < 2; spin++) {
        unsigned char bit = spin ? 2 : 1;
        short lst[NOCC];
        int cnt = 0;
        for (int n = 0; n < NSITE && cnt < NOCC; n++)
            if (c[n] & bit) lst[cnt++] = (short)n;
        int c1 = cnt;
        for (int n = 0; n < NSITE && cnt < NOCC; n++)
            if (!(c[n] & bit)) lst[cnt++] = (short)n;
        int p = 0, q = c1;
        for (int o = 0; o < NOCC; o++) {
            short v;
            bool takep = (p < c1) && (q >= NOCC || lst[p] < lst[q]);
            if (takep) v = lst[p++]; else v = lst[q++];
            g_site[spin][b][o] = v;
            g_tok[spin][b][o]  = c[v];
        }
    }
}

// ---------------------------------------------------------------------------
// LU chunk: REDUX.MAX argmax; uniform retired-row masks for parity;
// pivot row broadcast via double-buffered smem float4; float log2f pivot
// accumulation (no FP64 in the loop).
template<int NC>
__device__ __forceinline__ void lu_chunk(
    int steps, float (&a)[NOCC], float (&bb)[NOCC],
    unsigned& mask0, unsigned& mask1, bool has1, int lane,
    float& lmag, int& inv, int& nneg, bool& zerod, float4* u4, int& par)
{
    constexpr int NQ = (NC >> 2) + 1;
    const unsigned FULL = 0xffffffffu;

#pragma unroll 1
    for (int s = 0; s < steps; s++) {
        float4* ub = u4 + ((par ^= 1) ? 13 : 0);

        bool alive0 = !((mask0 >> lane) & 1u);
        bool alive1 = has1 && !((mask1 >> lane) & 1u);

        // ---- argmax |col0| over alive rows (key: mag[31:6] | 63-row) ----
        unsigned key = 0u;
        if (alive0)
            key = (__float_as_uint(fabsf(a[0])) & 0xFFFFFFC0u) | (unsigned)(63 - lane);
        if (alive1) {
            unsigned k1 = (__float_as_uint(fabsf(bb[0])) & 0xFFFFFFC0u) | (unsigned)(31 - lane);
            if (k1 > key) key = k1;
        }
        unsigned mx = __reduce_max_sync(FULL, key);
        int p   = 63 - (int)(mx & 63u);        // pivot row, warp-uniform
        int src = p & 31;
        bool top = (p < 32);

        // ---- pivot lane stores its row INCLUDING col0 ----
        if (top) {
            if (lane == src) {
#pragma unroll
                for (int q = 0; q < NQ; q++)
                    ub[q] = make_float4(
                        a[4 * q],
                        (4 * q + 1 <= NC) ? a[4 * q + 1] : 0.f,
                        (4 * q + 2 <= NC) ? a[4 * q + 2] : 0.f,
                        (4 * q + 3 <= NC) ? a[4 * q + 3] : 0.f);
            }
        } else {
            if (lane == src) {
#pragma unroll
                for (int q = 0; q < NQ; q++)
                    ub[q] = make_float4(
                        bb[4 * q],
                        (4 * q + 1 <= NC) ? bb[4 * q + 1] : 0.f,
                        (4 * q + 2 <= NC) ? bb[4 * q + 2] : 0.f,
                        (4 * q + 3 <= NC) ? bb[4 * q + 3] : 0.f);
            }
        }
        __syncwarp();

        // ---- parity from uniform masks ----
        if (top) {
            inv += __popc(mask0 & (0xFFFFFFFEu << p)) + __popc(mask1);
            mask0 |= 1u << p;
        } else {
            inv += __popc(mask1 & (0xFFFFFFFEu << (p - 32)));
            mask1 |= 1u << (p - 32);
        }

        // ---- update ----
        float4 U0 = ub[0];
        float piv = U0.x;
        if (piv == 0.f) zerod = true;
        lmag += log2f(fabsf(piv));
        nneg += (piv < 0.f) ? 1 : 0;

        float ninv = -1.0f / piv;
        float ma = a[0]  * ninv;   // pivot row -> -1 (self-zeroes); dead -> 0
        float mb = bb[0] * ninv;

        {
            if (1 <= NC) { a[0] = fmaf(ma, U0.y, a[1]); bb[0] = fmaf(mb, U0.y, bb[1]); }
            if (2 <= NC) { a[1] = fmaf(ma, U0.z, a[2]); bb[1] = fmaf(mb, U0.z, bb[2]); }
            if (3 <= NC) { a[2] = fmaf(ma, U0.w, a[3]); bb[2] = fmaf(mb, U0.w, bb[3]); }
        }
#pragma unroll
        for (int q = 1; q < NQ; q++) {
            float4 U = ub[q];
            {                      a[4 * q - 1] = fmaf(ma, U.x, a[4 * q]);
                                   bb[4 * q - 1]= fmaf(mb, U.x, bb[4 * q]); }
            if (4 * q + 1 <= NC) { a[4 * q]     = fmaf(ma, U.y, a[4 * q + 1]);
                                   bb[4 * q]    = fmaf(mb, U.y, bb[4 * q + 1]); }
            if (4 * q + 2 <= NC) { a[4 * q + 1] = fmaf(ma, U.z, a[4 * q + 2]);
                                   bb[4 * q + 1]= fmaf(mb, U.z, bb[4 * q + 2]); }
            if (4 * q + 3 <= NC) { a[4 * q + 2] = fmaf(ma, U.w, a[4 * q + 3]);
                                   bb[4 * q + 2]= fmaf(mb, U.w, bb[4 * q + 3]); }
        }
        // next step writes the other buffer; its REDUX+syncwarp order reuse
    }
}

// ---------------------------------------------------------------------------
// 16 CTAs/SM target -> 128-reg cap -> 4 warps per SMSP (was 3).
__global__ void __launch_bounds__(32, 16) k_main() {
    __shared__ float4 ubuf[26];

    int idx  = blockIdx.x;
    int b    = idx >> 3;
    int rr   = idx & 7;
    int spin = rr >> 2;
    int kk   = rr & 3;
    int lane = threadIdx.x;

    int r1 = 32 + lane;
    bool has1 = (lane < 18);

    int colbase = spin * 200 + kk * 50;

    int s0 = g_site[spin][b][lane];
    int t0 = g_tok[spin][b][lane];
    int s1 = has1 ? (int)g_site[spin][b][r1] : 0;
    int t1 = has1 ? (int)g_tok[spin][b][r1] : 0;

    const float* TW0 = g_TW + t0 * NORB + colbase;
    const float* PW0 = g_PW + s0 * NORB + colbase;
    const float* TW1 = g_TW + t1 * NORB + colbase;
    const float* PW1 = g_PW + s1 * NORB + colbase;

    float a[NOCC], bb[NOCC];
#pragma unroll
    for (int c = 0; c < NOCC; c++) {
        a[c] = TW0[c] + PW0[c];
        float v1 = TW1[c] + PW1[c];
        bb[c] = has1 ? v1 : 0.f;
    }

    unsigned mask0 = 0u;                       // retired rows 0..31
    unsigned mask1 = 0xFFFFFFFFu << 18;        // rows 50..63 never exist
    float lmag = 0.f;
    int   inv  = 0;
    int   nneg = 0;
    bool  zerod = false;
    int   par  = 0;

    // 10 chunks of 5 steps; trailing width bound shrinks by 5 each chunk.
    lu_chunk<49>(5, a, bb, mask0, mask1, has1, lane, lmag, inv, nneg, zerod, ubuf, par);
    lu_chunk<44>(5, a, bb, mask0, mask1, has1, lane, lmag, inv, nneg, zerod, ubuf, par);
    lu_chunk<39>(5, a, bb, mask0, mask1, has1, lane, lmag, inv, nneg, zerod, ubuf, par);
    lu_chunk<34>(5, a, bb, mask0, mask1, has1, lane, lmag, inv, nneg, zerod, ubuf, par);
    lu_chunk<29>(5, a, bb, mask0, mask1, has1, lane, lmag, inv, nneg, zerod, ubuf, par);
    lu_chunk<24>(5, a, bb, mask0, mask1, has1, lane, lmag, inv, nneg, zerod, ubuf, par);
    lu_chunk<19>(5, a, bb, mask0, mask1, has1, lane, lmag, inv, nneg, zerod, ubuf, par);
    lu_chunk<14>(5, a, bb, mask0, mask1, has1, lane, lmag, inv, nneg, zerod, ubuf, par);
    lu_chunk<9> (5, a, bb, mask0, mask1, has1, lane, lmag, inv, nneg, zerod, ubuf, par);
    lu_chunk<4> (5, a, bb, mask0, mask1, has1, lane, lmag, inv, nneg, zerod, ubuf, par);

    if (lane == 0) {
        float sgn = zerod ? 0.f : (((inv + nneg) & 1) ? -1.f : 1.f);
        g_logdet[spin][b][kk] = lmag;
        g_sgndet[spin][b][kk] = sgn;
    }
}

// ---------------------------------------------------------------------------
__global__ void k_combine(float* __restrict__ out, int out_elems) {
    int b = blockIdx.x * blockDim.x + threadIdx.x;
    if (b >= BATCH) return;

    float L[KDET], S[KDET];
    float M = -1e30f;
    for (int k = 0; k < KDET; k++) {
        S[k] = g_sgndet[0][b][k] * g_sgndet[1][b][k];
        L[k] = g_logdet[0][b][k] + g_logdet[1][b][k];
        if (S[k] != 0.f && L[k] > M) M = L[k];
    }
    float psis = 0.f;
    for (int k = 0; k < KDET; k++)
        if (S[k] != 0.f) psis += S[k] * exp2f(L[k] - M);

    double apsi = fabs((double)psis) * exp2((double)M);
    float la = (float)log(apsi + 1e-30);
    float ph = (psis >= 0.f) ? 0.f : 3.14159265358979323846f;

    if (out_elems == BATCH) {
        out[b] = la;
    } else {
        out[2 * b]     = la;
        out[2 * b + 1] = ph;
    }
}

// ---------------------------------------------------------------------------
extern "C" void kernel_launch(void* const* d_in, const int* in_sizes, int n_in,
                              void* d_out, int out_size) {
    InArgs a;
    a.n = (n_in < 8) ? n_in : 8;
    for (int i = 0; i < 8; i++) {
        a.p[i]  = (i < n_in) ? d_in[i] : d_in[0];
        a.sz[i] = (i < n_in) ? (long long)in_sizes[i] : 0;
    }

    k_resolve<<<1, 32>>>(a);
    k_prep   <<<TAB_BLK + IDX_BLK, 256>>>();
    k_main   <<<BATCH * 2 * KDET, 32>>>();
    k_combine<<<IDX_BLK, 256>>>((float*)d_out, out_size);
}